// round 14
// baseline (speedup 1.0000x reference)
#include <cuda_runtime.h>
#include <math.h>
#include <stdint.h>

// Problem dims
#define B_   32
#define L_   4096
#define DIN  16
#define H_   128
#define N2_  32
#define NL_  4
#define DOUT 8

// ---------------- scratch (device globals; no allocations allowed) ----------
__device__ float g_u[B_ * H_ * L_];       // running activation, (b,h,l)
__device__ float g_y[B_ * H_ * L_];       // conv+gelu output, (b,h,l)
__device__ float g_wre[NL_ * H_ * N2_];
__device__ float g_wim[NL_ * H_ * N2_];
__device__ float g_c1[NL_ * H_ * N2_];
__device__ float g_c2[NL_ * H_ * N2_];
__device__ float g_pool[B_ * H_];

typedef unsigned long long u64;

// ---------------- f32x2 packed FMA helpers (Blackwell FFMA2) ----------------
__device__ __forceinline__ u64 pack2(float a, float b) {
    u64 r;
    asm("mov.b64 %0, {%1,%2};" : "=l"(r) : "f"(a), "f"(b));
    return r;
}
__device__ __forceinline__ void unpack2(u64 v, float& a, float& b) {
    asm("mov.b64 {%0,%1}, %2;" : "=f"(a), "=f"(b) : "l"(v));
}
__device__ __forceinline__ u64 fma2(u64 a, u64 b, u64 c) {
    u64 d;
    asm("fma.rn.f32x2 %0, %1, %2, %3;" : "=l"(d) : "l"(a), "l"(b), "l"(c));
    return d;
}

__device__ __forceinline__ float sigmoidf_(float x) {
    return 1.0f / (1.0f + expf(-x));
}

__device__ __forceinline__ void cp16(unsigned saddr, const void* gaddr) {
    asm volatile("cp.async.cg.shared.global [%0], [%1], 16;"
                 :: "r"(saddr), "l"(gaddr));
}
__device__ __forceinline__ void cp_commit() {
    asm volatile("cp.async.commit_group;");
}
__device__ __forceinline__ void cp_wait1() {
    asm volatile("cp.async.wait_group 1;");
}

// ---------------- kernel 0: precompute SSM coefficients ---------------------
__global__ void precompute_kernel(const float* __restrict__ log_dt,
                                  const float* __restrict__ log_A_real,
                                  const float* __restrict__ A_imag,
                                  const float* __restrict__ C_re,
                                  const float* __restrict__ C_im) {
    int idx = blockIdx.x * blockDim.x + threadIdx.x;   // NL*H*N2 = 16384
    if (idx >= NL_ * H_ * N2_) return;
    int l = idx / (H_ * N2_);
    int h = (idx / N2_) % H_;

    float dt  = expf(log_dt[l * H_ + h]);
    float are = -expf(log_A_real[idx]);
    float aim = A_imag[idx];
    float dre = dt * are;
    float dim = dt * aim;
    float m   = expf(dre);
    float wre = m * cosf(dim);
    float wim = m * sinf(dim);
    // (w - 1) / A
    float nre = wre - 1.0f, nim = wim;
    float den = are * are + aim * aim;
    float inv = 1.0f / den;
    float qre = (nre * are + nim * aim) * inv;
    float qim = (nim * are - nre * aim) * inv;
    float cre = C_re[idx], cim = C_im[idx];
    float tre = cre * qre - cim * qim;
    float tim = cre * qim + cim * qre;
    g_wre[idx] = wre;
    g_wim[idx] = wim;
    g_c1[idx]  = 2.0f * tre;
    g_c2[idx]  = -2.0f * tim;
}

// ---------------- kernel 1: encoder  u[b,h,l] = x[b,l,:]·enc_w[h,:] + b -----
__global__ void encoder_kernel(const float* __restrict__ x,
                               const float* __restrict__ enc_w,
                               const float* __restrict__ enc_b) {
    __shared__ float sx[64 * 17];   // [p][d], padded
    __shared__ float sw[H_ * DIN];
    __shared__ float sb[H_];
    int t = threadIdx.x;            // 256
    int b = blockIdx.y;
    int l0 = blockIdx.x * 64;

    const float* xb = x + ((size_t)b * L_ + l0) * DIN;
    for (int i = t; i < 64 * DIN; i += 256) {
        int p = i >> 4, d = i & 15;
        sx[p * 17 + d] = xb[i];
    }
    for (int i = t; i < H_ * DIN; i += 256) sw[i] = enc_w[i];
    if (t < H_) sb[t] = enc_b[t];
    __syncthreads();

    int ubase = b * H_ * L_;
    for (int i = t; i < H_ * 64; i += 256) {
        int h = i >> 6, p = i & 63;
        float acc = sb[h];
#pragma unroll
        for (int d = 0; d < DIN; d++)
            acc = fmaf(sw[(h << 4) + d], sx[p * 17 + d], acc);
        g_u[ubase + (h << 12) + l0 + p] = acc;
    }
}

// ---------------- kernel 2: SSM scan + D skip + GELU ------------------------
// v7: ONE sequence per warp; 32 lanes x 1 complex state each (N2=32).
// 16-step windows keep register arrays at 32 floats -> no spills under the
// 73-reg cap (7 blocks/SM). Reduce-scatter 16 values over 32 lanes
// (masks 16/8/4/2, 15 shfl) + one xor-1 allreduce; lane l holds step l>>1,
// even lanes store.
__global__ void __launch_bounds__(128, 7)
scan_kernel(int layer, const float* __restrict__ Dl) {
    const unsigned F = 0xffffffffu;
    int t = threadIdx.x;                      // 128
    int seq = blockIdx.x * 4 + (t >> 5);      // 0..4095 = B*H-1
    int lane = t & 31;
    int h = seq & (H_ - 1);

    const float* z = g_u + (size_t)seq * L_;
    float* yo = g_y + (size_t)seq * L_;

    int cb = layer * (H_ * N2_) + h * N2_ + lane;  // one state per lane
    float wre = g_wre[cb], wim = g_wim[cb];
    float c1  = g_c1[cb],  c2  = g_c2[cb];
    float nwim = -wim;
    float Dh = Dl[h];

    float re = 0.f, im = 0.f;
    bool q16 = (lane & 16) != 0;
    bool q8  = (lane & 8) != 0;
    bool q4  = (lane & 4) != 0;
    bool q2  = (lane & 2) != 0;
    int myStep = lane >> 1;                   // step index this lane ends with

    const float4* z4 = (const float4*)z;

    for (int t0 = 0; t0 < L_; t0 += 16) {
        int zb = t0 >> 2;
        float4 b0 = z4[zb + 0], b1 = z4[zb + 1];
        float4 b2 = z4[zb + 2], b3 = z4[zb + 3];

        float zc[16] = {b0.x, b0.y, b0.z, b0.w,  b1.x, b1.y, b1.z, b1.w,
                        b2.x, b2.y, b2.z, b2.w,  b3.x, b3.y, b3.z, b3.w};
        float s[16];
#pragma unroll
        for (int j = 0; j < 16; j++) {
            float t1  = fmaf(nwim, im, zc[j]);
            float nre = fmaf(wre, re, t1);
            float nim = fmaf(wim, re, wre * im);
            re = nre; im = nim;
            s[j] = fmaf(c1, re, c2 * im);
        }
        // reduce-scatter 16 values over 32 lanes (4 rounds), then xor-1
        // allreduce; lane l ends with s[0] = total for step (l>>1).
#pragma unroll
        for (int r = 0; r < 8; r++) {
            float send = q16 ? s[r] : s[r + 8];
            float recv = __shfl_xor_sync(F, send, 16);
            s[r] = (q16 ? s[r + 8] : s[r]) + recv;
        }
#pragma unroll
        for (int r = 0; r < 4; r++) {
            float send = q8 ? s[r] : s[r + 4];
            float recv = __shfl_xor_sync(F, send, 8);
            s[r] = (q8 ? s[r + 4] : s[r]) + recv;
        }
#pragma unroll
        for (int r = 0; r < 2; r++) {
            float send = q4 ? s[r] : s[r + 2];
            float recv = __shfl_xor_sync(F, send, 4);
            s[r] = (q4 ? s[r + 2] : s[r]) + recv;
        }
        {
            float send = q2 ? s[0] : s[1];
            float recv = __shfl_xor_sync(F, send, 2);
            s[0] = (q2 ? s[1] : s[0]) + recv;
        }
        s[0] += __shfl_xor_sync(F, s[0], 1);

        float zstep = z[t0 + myStep];
        float yraw = fmaf(Dh, zstep, s[0]);
        float gv = 0.5f * yraw * (1.0f + erff(yraw * 0.7071067811865475f));
        if ((lane & 1) == 0) yo[t0 + myStep] = gv;
    }
}

// ---------------- kernel 3: PERSISTENT fused 1x1 conv -> GLU -> LN ----------
// 148 blocks x 512 threads; each block owns ~7 tiles of (b, 128 positions).
// Weights staged transposed ONCE per block. y streamed in 32-h chunks,
// double-buffered via cp.async; acc[8][4] accumulates across chunks.
// Warp w owns a-rows [w*8, w*8+8) AND g-rows [128+w*8, ...) -> register GLU.
#define WT_STRIDE 260
#define TILE_P 128
#define CH_H   32
#define N_TILES (B_ * (L_ / TILE_P))     // 1024
#define GLU_GRID 148
#define GLU_SMEM_FLOATS (33280 + 8192 + 4096 + 256 + 256 + 256)
__global__ void __launch_bounds__(512, 1)
glu_ln_kernel(const float* __restrict__ conv_w_l,
              const float* __restrict__ conv_b_l,
              const float* __restrict__ ln_w_l,
              const float* __restrict__ ln_b_l) {
    extern __shared__ float sm[];
    float* sWt   = sm;                 // 128*260 transposed weights [h][o]
    float* sYa   = sm + 33280;         // 4096 : y chunk [h'][p] (32h x 128p)
    float* sYb   = sm + 37376;         // 4096
    float* sPS   = sm + 41472;         // 2048 : [warp][p]
    float* sPQ   = sm + 43520;         // 2048
    float* sBias = sm + 45568;         // 256
    float* sLnw  = sm + 45824;         // 128
    float* sLnb  = sm + 45952;         // 128
    float* sMu   = sm + 46080;         // 128
    float* sRs   = sm + 46208;         // 128

    int t = threadIdx.x;               // 512
    int w = t >> 5, lane = t & 31;

    // ---- one-time staging: transposed weights ----
    {
        int hh = t & 127;
        int oqb = (t >> 7) << 4;       // 0,16,32,48
#pragma unroll
        for (int k = 0; k < 16; k++) {
            int o = (oqb + k) << 2;
            float4 v;
            v.x = conv_w_l[(o + 0) * 128 + hh];
            v.y = conv_w_l[(o + 1) * 128 + hh];
            v.z = conv_w_l[(o + 2) * 128 + hh];
            v.w = conv_w_l[(o + 3) * 128 + hh];
            *(float4*)&sWt[hh * WT_STRIDE + o] = v;
        }
    }
    if (t < 256) sBias[t] = conv_b_l[t];
    if (t < 128) { sLnw[t] = ln_w_l[t]; sLnb[t] = ln_b_l[t]; }

    int p0 = lane << 2;                // 4 positions per lane
    int woff = w << 3;                 // warp channel base (0..127)

    // ---- prefetch chunk 0 of first tile ----
    int tile = blockIdx.x;
    {
        int b = tile >> 5, l0 = (tile & 31) << 7;
        int ub = b * H_ * L_ + l0;
#pragma unroll
        for (int k = 0; k < 2; k++) {
            int idx = t + k * 512;     // 1024 float4 per chunk
            int h = idx >> 5, p4 = idx & 31;
            cp16((unsigned)__cvta_generic_to_shared(&sYa[(h << 7) + (p4 << 2)]),
                 &g_y[ub + (h << 12) + (p4 << 2)]);
        }
    }
    cp_commit();
    int cur = 0;

    for (; tile < N_TILES; tile += GLU_GRID) {
        int b = tile >> 5, l0 = (tile & 31) << 7;
        int ubase = b * H_ * L_;

        u64 acc[8][4];                 // [pair: 0-3 = a, 4-7 = g][position]
#pragma unroll
        for (int j = 0; j < 8; j++)
#pragma unroll
            for (int p = 0; p < 4; p++) acc[j][p] = 0ull;

#pragma unroll
        for (int c = 0; c < 4; c++) {
            float* bufc = cur ? sYb : sYa;
            float* bufn = cur ? sYa : sYb;
            // prefetch next chunk (or chunk 0 of the next tile)
            int ptile = (c < 3) ? tile : tile + GLU_GRID;
            int pch   = (c < 3) ? c + 1 : 0;
            if (ptile < N_TILES) {
                int pb = ptile >> 5, pl0 = (ptile & 31) << 7;
                int ub = pb * H_ * L_ + (pch * CH_H << 12) + pl0;
#pragma unroll
                for (int k = 0; k < 2; k++) {
                    int idx = t + k * 512;
                    int h = idx >> 5, p4 = idx & 31;
                    cp16((unsigned)__cvta_generic_to_shared(
                             &bufn[(h << 7) + (p4 << 2)]),
                         &g_y[ub + (h << 12) + (p4 << 2)]);
                }
            }
            cp_commit();
            cp_wait1();                // current chunk resident
            __syncthreads();

            int hbase = c * CH_H;
#pragma unroll 4
            for (int hh = 0; hh < CH_H; hh++) {
                float4 yv = *(const float4*)&bufc[(hh << 7) + p0];
                u64 ys0 = pack2(yv.x, yv.x);
                u64 ys1 = pack2(yv.y, yv.y);
                u64 ys2 = pack2(yv.z, yv.z);
                u64 ys3 = pack2(yv.w, yv.w);
                const float* wr = &sWt[(hbase + hh) * WT_STRIDE + woff];
                ulonglong2 wa = *(const ulonglong2*)(wr);
                ulonglong2 wb = *(const ulonglong2*)(wr + 4);
                ulonglong2 wg = *(const ulonglong2*)(wr + 128);
                ulonglong2 wh2 = *(const ulonglong2*)(wr + 132);
                u64 wp[8] = {wa.x, wa.y, wb.x, wb.y,
                             wg.x, wg.y, wh2.x, wh2.y};
#pragma unroll
                for (int j = 0; j < 8; j++) {
                    acc[j][0] = fma2(wp[j], ys0, acc[j][0]);
                    acc[j][1] = fma2(wp[j], ys1, acc[j][1]);
                    acc[j][2] = fma2(wp[j], ys2, acc[j][2]);
                    acc[j][3] = fma2(wp[j], ys3, acc[j][3]);
                }
            }
            __syncthreads();           // all reads done before buffer refill
            cur ^= 1;
        }

        // ---- GLU + residual in registers ----
        float4 r[8];
        float4 s4 = make_float4(0.f, 0.f, 0.f, 0.f);
        float4 q4 = make_float4(0.f, 0.f, 0.f, 0.f);
#pragma unroll
        for (int c = 0; c < 8; c++) {
            int j = c >> 1;
            int ch = woff + c;
            float a0, a1, a2, a3, g0, g1, g2, g3;
            if (c & 1) {
                float xx;
                unpack2(acc[j][0], xx, a0);
                unpack2(acc[j][1], xx, a1);
                unpack2(acc[j][2], xx, a2);
                unpack2(acc[j][3], xx, a3);
                unpack2(acc[j + 4][0], xx, g0);
                unpack2(acc[j + 4][1], xx, g1);
                unpack2(acc[j + 4][2], xx, g2);
                unpack2(acc[j + 4][3], xx, g3);
            } else {
                float xx;
                unpack2(acc[j][0], a0, xx);
                unpack2(acc[j][1], a1, xx);
                unpack2(acc[j][2], a2, xx);
                unpack2(acc[j][3], a3, xx);
                unpack2(acc[j + 4][0], g0, xx);
                unpack2(acc[j + 4][1], g1, xx);
                unpack2(acc[j + 4][2], g2, xx);
                unpack2(acc[j + 4][3], g3, xx);
            }
            float ba = sBias[ch], bg = sBias[128 + ch];
            float4 u4 = *(const float4*)&g_u[ubase + (ch << 12) + l0 + p0];
            r[c].x = fmaf(a0 + ba, sigmoidf_(g0 + bg), u4.x);
            r[c].y = fmaf(a1 + ba, sigmoidf_(g1 + bg), u4.y);
            r[c].z = fmaf(a2 + ba, sigmoidf_(g2 + bg), u4.z);
            r[c].w = fmaf(a3 + ba, sigmoidf_(g3 + bg), u4.w);
            s4.x += r[c].x; s4.y += r[c].y; s4.z += r[c].z; s4.w += r[c].w;
            q4.x = fmaf(r[c].x, r[c].x, q4.x);
            q4.y = fmaf(r[c].y, r[c].y, q4.y);
            q4.z = fmaf(r[c].z, r[c].z, q4.z);
            q4.w = fmaf(r[c].w, r[c].w, q4.w);
        }
        *(float4*)&sPS[(w << 7) + p0] = s4;
        *(float4*)&sPQ[(w << 7) + p0] = q4;
        __syncthreads();

        if (t < 128) {
            float S = 0.f, Q = 0.f;
#pragma unroll
            for (int ww = 0; ww < 16; ww++) {
                S += sPS[(ww << 7) + t];
                Q += sPQ[(ww << 7) + t];
            }
            float mu = S * (1.0f / H_);
            float var = Q * (1.0f / H_) - mu * mu;
            sMu[t] = mu;
            sRs[t] = rsqrtf(var + 1e-5f);
        }
        __syncthreads();

        float4 mu4 = *(const float4*)&sMu[p0];
        float4 rs4 = *(const float4*)&sRs[p0];
#pragma unroll
        for (int c = 0; c < 8; c++) {
            int ch = woff + c;
            float lw = sLnw[ch], lb = sLnb[ch];
            float4 v;
            v.x = (r[c].x - mu4.x) * rs4.x * lw + lb;
            v.y = (r[c].y - mu4.y) * rs4.y * lw + lb;
            v.z = (r[c].z - mu4.z) * rs4.z * lw + lb;
            v.w = (r[c].w - mu4.w) * rs4.w * lw + lb;
            *(float4*)&g_u[ubase + (ch << 12) + l0 + p0] = v;
        }
    }
}

// ---------------- kernel 4: mean-pool over L --------------------------------
__global__ void pool_kernel() {
    __shared__ float red[256];
    int t = threadIdx.x;
    const float* p = g_u + (size_t)blockIdx.x * L_;
    float s = 0.f;
    for (int i = t; i < L_; i += 256) s += p[i];
    red[t] = s;
    __syncthreads();
    for (int k = 128; k > 0; k >>= 1) {
        if (t < k) red[t] += red[t + k];
        __syncthreads();
    }
    if (t == 0) g_pool[blockIdx.x] = red[0] * (1.0f / L_);
}

// ---------------- kernel 5: decoder -----------------------------------------
__global__ void decode_kernel(const float* __restrict__ dec_w,
                              const float* __restrict__ dec_b,
                              float* __restrict__ pred) {
    int t = threadIdx.x;
    if (t >= B_ * DOUT) return;
    int b = t >> 3, o = t & 7;
    float acc = dec_b[o];
    for (int h = 0; h < H_; h++)
        acc = fmaf(dec_w[o * H_ + h], g_pool[b * H_ + h], acc);
    pred[t] = 1.0f / (1.0f + expf(-acc));
}

// ---------------- kernel 6: transpose (b,h,l) -> emb (b,l,h) -----------------
__global__ void transpose_kernel(float* __restrict__ emb) {
    __shared__ float tile[32][33];
    int b = blockIdx.z;
    int h0 = blockIdx.y * 32;
    int l0 = blockIdx.x * 32;
    int tx = threadIdx.x, ty = threadIdx.y;
#pragma unroll
    for (int i = 0; i < 32; i += 8)
        tile[ty + i][tx] = g_u[((b * H_ + h0 + ty + i) << 12) + l0 + tx];
    __syncthreads();
#pragma unroll
    for (int i = 0; i < 32; i += 8)
        emb[((size_t)(b * L_ + l0 + ty + i)) * H_ + h0 + tx] = tile[tx][ty + i];
}

// ---------------- launch ------------------------------------------------------
extern "C" void kernel_launch(void* const* d_in, const int* in_sizes, int n_in,
                              void* d_out, int out_size) {
    const float* x          = (const float*)d_in[0];
    // d_in[1] = times (unused)
    const float* enc_w      = (const float*)d_in[2];
    const float* enc_b      = (const float*)d_in[3];
    const float* log_dt     = (const float*)d_in[4];
    const float* log_A_real = (const float*)d_in[5];
    const float* A_imag     = (const float*)d_in[6];
    const float* C_re       = (const float*)d_in[7];
    const float* C_im       = (const float*)d_in[8];
    const float* Dskip      = (const float*)d_in[9];
    const float* conv_w     = (const float*)d_in[10];
    const float* conv_b     = (const float*)d_in[11];
    const float* ln_w       = (const float*)d_in[12];
    const float* ln_b       = (const float*)d_in[13];
    const float* dec_w      = (const float*)d_in[14];
    const float* dec_b      = (const float*)d_in[15];

    float* out = (float*)d_out;
    float* pred = out;           // (B, DOUT) = 256 floats
    float* emb  = out + B_ * DOUT;

    static const size_t glu_smem = GLU_SMEM_FLOATS * sizeof(float);
    cudaFuncSetAttribute(glu_ln_kernel,
                         cudaFuncAttributeMaxDynamicSharedMemorySize,
                         (int)glu_smem);

    precompute_kernel<<<(NL_ * H_ * N2_ + 255) / 256, 256>>>(
        log_dt, log_A_real, A_imag, C_re, C_im);

    encoder_kernel<<<dim3(L_ / 64, B_), 256>>>(x, enc_w, enc_b);

    for (int l = 0; l < NL_; l++) {
        scan_kernel<<<1024, 128>>>(l, Dskip + l * H_);
        glu_ln_kernel<<<GLU_GRID, 512, glu_smem>>>(
            conv_w + (size_t)l * 2 * H_ * H_,
            conv_b + (size_t)l * 2 * H_,
            ln_w + (size_t)l * H_,
            ln_b + (size_t)l * H_);
    }

    pool_kernel<<<B_ * H_, 256>>>();
    decode_kernel<<<1, 256>>>(dec_w, dec_b, pred);
    transpose_kernel<<<dim3(L_ / 32, H_ / 32, B_), dim3(32, 8)>>>(emb);
}

// round 15
// speedup vs baseline: 1.0974x; 1.0974x over previous
#include <cuda_runtime.h>
#include <math.h>
#include <stdint.h>

// Problem dims
#define B_   32
#define L_   4096
#define DIN  16
#define H_   128
#define N2_  32
#define NL_  4
#define DOUT 8

// ---------------- scratch (device globals; no allocations allowed) ----------
__device__ float g_u[B_ * H_ * L_];       // running activation, (b,h,l)
__device__ float g_y[B_ * H_ * L_];       // conv+gelu output, (b,h,l)
__device__ float g_wre[NL_ * H_ * N2_];
__device__ float g_wim[NL_ * H_ * N2_];
__device__ float g_c1[NL_ * H_ * N2_];
__device__ float g_c2[NL_ * H_ * N2_];
__device__ float g_pool[B_ * H_];
__device__ float g_poolpart[B_ * H_ * 32];

typedef unsigned long long u64;

// ---------------- f32x2 packed FMA helpers (Blackwell FFMA2) ----------------
__device__ __forceinline__ u64 pack2(float a, float b) {
    u64 r;
    asm("mov.b64 %0, {%1,%2};" : "=l"(r) : "f"(a), "f"(b));
    return r;
}
__device__ __forceinline__ void unpack2(u64 v, float& a, float& b) {
    asm("mov.b64 {%0,%1}, %2;" : "=f"(a), "=f"(b) : "l"(v));
}
__device__ __forceinline__ u64 fma2(u64 a, u64 b, u64 c) {
    u64 d;
    asm("fma.rn.f32x2 %0, %1, %2, %3;" : "=l"(d) : "l"(a), "l"(b), "l"(c));
    return d;
}

__device__ __forceinline__ float sigmoidf_(float x) {
    return 1.0f / (1.0f + expf(-x));
}

__device__ __forceinline__ void cp16(unsigned saddr, const void* gaddr) {
    asm volatile("cp.async.cg.shared.global [%0], [%1], 16;"
                 :: "r"(saddr), "l"(gaddr));
}
__device__ __forceinline__ void cp_commit() {
    asm volatile("cp.async.commit_group;");
}
__device__ __forceinline__ void cp_wait1() {
    asm volatile("cp.async.wait_group 1;");
}

// ---------------- kernel 0: precompute SSM coefficients ---------------------
__global__ void precompute_kernel(const float* __restrict__ log_dt,
                                  const float* __restrict__ log_A_real,
                                  const float* __restrict__ A_imag,
                                  const float* __restrict__ C_re,
                                  const float* __restrict__ C_im) {
    int idx = blockIdx.x * blockDim.x + threadIdx.x;   // NL*H*N2 = 16384
    if (idx >= NL_ * H_ * N2_) return;
    int l = idx / (H_ * N2_);
    int h = (idx / N2_) % H_;

    float dt  = expf(log_dt[l * H_ + h]);
    float are = -expf(log_A_real[idx]);
    float aim = A_imag[idx];
    float dre = dt * are;
    float dim = dt * aim;
    float m   = expf(dre);
    float wre = m * cosf(dim);
    float wim = m * sinf(dim);
    // (w - 1) / A
    float nre = wre - 1.0f, nim = wim;
    float den = are * are + aim * aim;
    float inv = 1.0f / den;
    float qre = (nre * are + nim * aim) * inv;
    float qim = (nim * are - nre * aim) * inv;
    float cre = C_re[idx], cim = C_im[idx];
    float tre = cre * qre - cim * qim;
    float tim = cre * qim + cim * qre;
    g_wre[idx] = wre;
    g_wim[idx] = wim;
    g_c1[idx]  = 2.0f * tre;
    g_c2[idx]  = -2.0f * tim;
}

// ---------------- kernel 1: encoder  u[b,h,l] = x[b,l,:]·enc_w[h,:] + b -----
__global__ void encoder_kernel(const float* __restrict__ x,
                               const float* __restrict__ enc_w,
                               const float* __restrict__ enc_b) {
    __shared__ float sx[64 * 17];   // [p][d], padded
    __shared__ float sw[H_ * DIN];
    __shared__ float sb[H_];
    int t = threadIdx.x;            // 256
    int b = blockIdx.y;
    int l0 = blockIdx.x * 64;

    const float* xb = x + ((size_t)b * L_ + l0) * DIN;
    for (int i = t; i < 64 * DIN; i += 256) {
        int p = i >> 4, d = i & 15;
        sx[p * 17 + d] = xb[i];
    }
    for (int i = t; i < H_ * DIN; i += 256) sw[i] = enc_w[i];
    if (t < H_) sb[t] = enc_b[t];
    __syncthreads();

    int ubase = b * H_ * L_;
    for (int i = t; i < H_ * 64; i += 256) {
        int h = i >> 6, p = i & 63;
        float acc = sb[h];
#pragma unroll
        for (int d = 0; d < DIN; d++)
            acc = fmaf(sw[(h << 4) + d], sx[p * 17 + d], acc);
        g_u[ubase + (h << 12) + l0 + p] = acc;
    }
}

// ---------------- kernel 2: SSM scan + D skip + GELU (v8: pipelined) --------
// 16 lanes/seq, 2 complex states/lane (one f32x2 pair), 2 seqs/warp.
// Software pipelining: recurrence for block k+1 is issued BEFORE the
// shuffle-reduce of block k, so the two serial chains overlap.
__global__ void __launch_bounds__(128)
scan_kernel(int layer, const float* __restrict__ Dl) {
    const unsigned F = 0xffffffffu;
    const u64 Z0 = 0ull;
    int t = threadIdx.x;                    // 128
    int warpId = blockIdx.x * 4 + (t >> 5); // 0..2047
    int lane = t & 31;
    int lane16 = lane & 15;
    int g = lane >> 4;                      // 0/1
    int seq = warpId * 2 + g;               // 0 .. B*H-1
    int h = seq & (H_ - 1);

    const float* z = g_u + (size_t)seq * L_;
    float* yo = g_y + (size_t)seq * L_;

    int cb = layer * (H_ * N2_) + h * N2_ + lane16 * 2;
    u64 wre  = pack2(g_wre[cb], g_wre[cb + 1]);
    u64 wim  = pack2(g_wim[cb], g_wim[cb + 1]);
    u64 nwim = pack2(-g_wim[cb], -g_wim[cb + 1]);
    u64 d1   = pack2(g_c1[cb], g_c1[cb + 1]);
    u64 d2   = pack2(g_c2[cb], g_c2[cb + 1]);
    float Dh = Dl[h];

    u64 sre = Z0, sim = Z0;
    bool q8 = (lane16 & 8) != 0;
    bool q4 = (lane16 & 4) != 0;
    bool q2 = (lane16 & 2) != 0;
    bool q1 = (lane16 & 1) != 0;

    const float4* z4 = (const float4*)z;

    // ---- preamble: recurrence on block 0 ----
    float sp[16];
    {
        float4 a0 = z4[0], a1 = z4[1], a2 = z4[2], a3 = z4[3];
        float zc[16] = {a0.x, a0.y, a0.z, a0.w,  a1.x, a1.y, a1.z, a1.w,
                        a2.x, a2.y, a2.z, a2.w,  a3.x, a3.y, a3.z, a3.w};
#pragma unroll
        for (int j = 0; j < 16; j++) {
            u64 z2 = pack2(zc[j], zc[j]);
            u64 nre = fma2(wre, sre, fma2(nwim, sim, z2));
            u64 nim = fma2(wre, sim, fma2(wim, sre, Z0));
            sre = nre; sim = nim;
            u64 d = fma2(d1, sre, fma2(d2, sim, Z0));
            float lo, hi;
            unpack2(d, lo, hi);
            sp[j] = lo + hi;
        }
    }
    float zown_c = z[lane16];

    for (int t0 = 0; t0 < L_ - 16; t0 += 16) {
        // load next z block + own-z
        int nb = (t0 + 16) >> 2;
        float4 b0 = z4[nb], b1 = z4[nb + 1], b2 = z4[nb + 2], b3 = z4[nb + 3];
        float zown_n = z[t0 + 16 + lane16];

        // recurrence for block k+1 (independent of sp reduce below)
        float sc[16];
        {
            float zc[16] = {b0.x, b0.y, b0.z, b0.w,  b1.x, b1.y, b1.z, b1.w,
                            b2.x, b2.y, b2.z, b2.w,  b3.x, b3.y, b3.z, b3.w};
#pragma unroll
            for (int j = 0; j < 16; j++) {
                u64 z2 = pack2(zc[j], zc[j]);
                u64 nre = fma2(wre, sre, fma2(nwim, sim, z2));
                u64 nim = fma2(wre, sim, fma2(wim, sre, Z0));
                sre = nre; sim = nim;
                u64 d = fma2(d1, sre, fma2(d2, sim, Z0));
                float lo, hi;
                unpack2(d, lo, hi);
                sc[j] = lo + hi;
            }
        }

        // reduce block k (sp) — overlaps with recurrence above in issue order
#pragma unroll
        for (int r = 0; r < 8; r++) {
            float send = q8 ? sp[r] : sp[r + 8];
            float recv = __shfl_xor_sync(F, send, 8);
            sp[r] = (q8 ? sp[r + 8] : sp[r]) + recv;
        }
#pragma unroll
        for (int r = 0; r < 4; r++) {
            float send = q4 ? sp[r] : sp[r + 4];
            float recv = __shfl_xor_sync(F, send, 4);
            sp[r] = (q4 ? sp[r + 4] : sp[r]) + recv;
        }
#pragma unroll
        for (int r = 0; r < 2; r++) {
            float send = q2 ? sp[r] : sp[r + 2];
            float recv = __shfl_xor_sync(F, send, 2);
            sp[r] = (q2 ? sp[r + 2] : sp[r]) + recv;
        }
        {
            float send = q1 ? sp[0] : sp[1];
            float recv = __shfl_xor_sync(F, send, 1);
            sp[0] = (q1 ? sp[1] : sp[0]) + recv;
        }

        float yraw = fmaf(Dh, zown_c, sp[0]);
        float gv = 0.5f * yraw * (1.0f + erff(yraw * 0.7071067811865475f));
        yo[t0 + lane16] = gv;

#pragma unroll
        for (int j = 0; j < 16; j++) sp[j] = sc[j];
        zown_c = zown_n;
    }

    // ---- tail: reduce last block ----
#pragma unroll
    for (int r = 0; r < 8; r++) {
        float send = q8 ? sp[r] : sp[r + 8];
        float recv = __shfl_xor_sync(F, send, 8);
        sp[r] = (q8 ? sp[r + 8] : sp[r]) + recv;
    }
#pragma unroll
    for (int r = 0; r < 4; r++) {
        float send = q4 ? sp[r] : sp[r + 4];
        float recv = __shfl_xor_sync(F, send, 4);
        sp[r] = (q4 ? sp[r + 4] : sp[r]) + recv;
    }
#pragma unroll
    for (int r = 0; r < 2; r++) {
        float send = q2 ? sp[r] : sp[r + 2];
        float recv = __shfl_xor_sync(F, send, 2);
        sp[r] = (q2 ? sp[r + 2] : sp[r]) + recv;
    }
    {
        float send = q1 ? sp[0] : sp[1];
        float recv = __shfl_xor_sync(F, send, 1);
        sp[0] = (q1 ? sp[1] : sp[0]) + recv;
    }
    float yraw = fmaf(Dh, zown_c, sp[0]);
    float gv = 0.5f * yraw * (1.0f + erff(yraw * 0.7071067811865475f));
    yo[L_ - 16 + lane16] = gv;
}

// ---------------- kernel 3: PERSISTENT fused 1x1 conv -> GLU -> LN ----------
#define WT_STRIDE 260
#define TILE_P 128
#define CH_H   32
#define N_TILES (B_ * (L_ / TILE_P))     // 1024
#define GLU_GRID 148
#define GLU_SMEM_FLOATS (33280 + 8192 + 4096 + 256 + 256 + 256)

// Shared GEMM + GLU + LN-stats body; FINAL selects the epilogue.
template <int FINAL>
__device__ __forceinline__ void glu_body(
    const float* __restrict__ conv_w_l,
    const float* __restrict__ conv_b_l,
    const float* __restrict__ ln_w_l,
    const float* __restrict__ ln_b_l,
    float* __restrict__ emb) {
    extern __shared__ float sm[];
    float* sWt   = sm;                 // 128*260 transposed weights [h][o]
    float* sYa   = sm + 33280;         // 4096 : y chunk [h'][p] (32h x 128p)
    float* sYb   = sm + 37376;         // 4096
    float* sPS   = sm + 41472;         // 2048 : [warp][p]
    float* sPQ   = sm + 43520;         // 2048
    float* sBias = sm + 45568;         // 256
    float* sLnw  = sm + 45824;         // 128
    float* sLnb  = sm + 45952;         // 128
    float* sMu   = sm + 46080;         // 128
    float* sRs   = sm + 46208;         // 128

    int t = threadIdx.x;               // 512
    int w = t >> 5, lane = t & 31;

    // ---- one-time staging: transposed weights ----
    {
        int hh = t & 127;
        int oqb = (t >> 7) << 4;       // 0,16,32,48
#pragma unroll
        for (int k = 0; k < 16; k++) {
            int o = (oqb + k) << 2;
            float4 v;
            v.x = conv_w_l[(o + 0) * 128 + hh];
            v.y = conv_w_l[(o + 1) * 128 + hh];
            v.z = conv_w_l[(o + 2) * 128 + hh];
            v.w = conv_w_l[(o + 3) * 128 + hh];
            *(float4*)&sWt[hh * WT_STRIDE + o] = v;
        }
    }
    if (t < 256) sBias[t] = conv_b_l[t];
    if (t < 128) { sLnw[t] = ln_w_l[t]; sLnb[t] = ln_b_l[t]; }

    int p0 = lane << 2;                // 4 positions per lane
    int woff = w << 3;                 // warp channel base (0..127)

    // ---- prefetch chunk 0 of first tile ----
    int tile = blockIdx.x;
    {
        int b = tile >> 5, l0 = (tile & 31) << 7;
        int ub = b * H_ * L_ + l0;
#pragma unroll
        for (int k = 0; k < 2; k++) {
            int idx = t + k * 512;     // 1024 float4 per chunk
            int h = idx >> 5, p4 = idx & 31;
            cp16((unsigned)__cvta_generic_to_shared(&sYa[(h << 7) + (p4 << 2)]),
                 &g_y[ub + (h << 12) + (p4 << 2)]);
        }
    }
    cp_commit();
    int cur = 0;

    for (; tile < N_TILES; tile += GLU_GRID) {
        int b = tile >> 5, l0 = (tile & 31) << 7;
        int ubase = b * H_ * L_;

        u64 acc[8][4];                 // [pair: 0-3 = a, 4-7 = g][position]
#pragma unroll
        for (int j = 0; j < 8; j++)
#pragma unroll
            for (int p = 0; p < 4; p++) acc[j][p] = 0ull;

#pragma unroll
        for (int c = 0; c < 4; c++) {
            float* bufc = cur ? sYb : sYa;
            float* bufn = cur ? sYa : sYb;
            // prefetch next chunk (or chunk 0 of the next tile)
            int ptile = (c < 3) ? tile : tile + GLU_GRID;
            int pch   = (c < 3) ? c + 1 : 0;
            if (ptile < N_TILES) {
                int pb = ptile >> 5, pl0 = (ptile & 31) << 7;
                int ub = pb * H_ * L_ + (pch * CH_H << 12) + pl0;
#pragma unroll
                for (int k = 0; k < 2; k++) {
                    int idx = t + k * 512;
                    int h = idx >> 5, p4 = idx & 31;
                    cp16((unsigned)__cvta_generic_to_shared(
                             &bufn[(h << 7) + (p4 << 2)]),
                         &g_y[ub + (h << 12) + (p4 << 2)]);
                }
            }
            cp_commit();
            cp_wait1();                // current chunk resident
            __syncthreads();

            int hbase = c * CH_H;
#pragma unroll 4
            for (int hh = 0; hh < CH_H; hh++) {
                float4 yv = *(const float4*)&bufc[(hh << 7) + p0];
                u64 ys0 = pack2(yv.x, yv.x);
                u64 ys1 = pack2(yv.y, yv.y);
                u64 ys2 = pack2(yv.z, yv.z);
                u64 ys3 = pack2(yv.w, yv.w);
                const float* wr = &sWt[(hbase + hh) * WT_STRIDE + woff];
                ulonglong2 wa = *(const ulonglong2*)(wr);
                ulonglong2 wb = *(const ulonglong2*)(wr + 4);
                ulonglong2 wg = *(const ulonglong2*)(wr + 128);
                ulonglong2 wh2 = *(const ulonglong2*)(wr + 132);
                u64 wp[8] = {wa.x, wa.y, wb.x, wb.y,
                             wg.x, wg.y, wh2.x, wh2.y};
#pragma unroll
                for (int j = 0; j < 8; j++) {
                    acc[j][0] = fma2(wp[j], ys0, acc[j][0]);
                    acc[j][1] = fma2(wp[j], ys1, acc[j][1]);
                    acc[j][2] = fma2(wp[j], ys2, acc[j][2]);
                    acc[j][3] = fma2(wp[j], ys3, acc[j][3]);
                }
            }
            __syncthreads();           // all reads done before buffer refill
            cur ^= 1;
        }

        // ---- GLU + residual in registers ----
        float4 r[8];
        float4 s4 = make_float4(0.f, 0.f, 0.f, 0.f);
        float4 q4v = make_float4(0.f, 0.f, 0.f, 0.f);
#pragma unroll
        for (int c = 0; c < 8; c++) {
            int j = c >> 1;
            int ch = woff + c;
            float a0, a1, a2, a3, g0, g1, g2, g3;
            if (c & 1) {
                float xx;
                unpack2(acc[j][0], xx, a0);
                unpack2(acc[j][1], xx, a1);
                unpack2(acc[j][2], xx, a2);
                unpack2(acc[j][3], xx, a3);
                unpack2(acc[j + 4][0], xx, g0);
                unpack2(acc[j + 4][1], xx, g1);
                unpack2(acc[j + 4][2], xx, g2);
                unpack2(acc[j + 4][3], xx, g3);
            } else {
                float xx;
                unpack2(acc[j][0], a0, xx);
                unpack2(acc[j][1], a1, xx);
                unpack2(acc[j][2], a2, xx);
                unpack2(acc[j][3], a3, xx);
                unpack2(acc[j + 4][0], g0, xx);
                unpack2(acc[j + 4][1], g1, xx);
                unpack2(acc[j + 4][2], g2, xx);
                unpack2(acc[j + 4][3], g3, xx);
            }
            float ba = sBias[ch], bg = sBias[128 + ch];
            float4 u4 = *(const float4*)&g_u[ubase + (ch << 12) + l0 + p0];
            r[c].x = fmaf(a0 + ba, sigmoidf_(g0 + bg), u4.x);
            r[c].y = fmaf(a1 + ba, sigmoidf_(g1 + bg), u4.y);
            r[c].z = fmaf(a2 + ba, sigmoidf_(g2 + bg), u4.z);
            r[c].w = fmaf(a3 + ba, sigmoidf_(g3 + bg), u4.w);
            s4.x += r[c].x; s4.y += r[c].y; s4.z += r[c].z; s4.w += r[c].w;
            q4v.x = fmaf(r[c].x, r[c].x, q4v.x);
            q4v.y = fmaf(r[c].y, r[c].y, q4v.y);
            q4v.z = fmaf(r[c].z, r[c].z, q4v.z);
            q4v.w = fmaf(r[c].w, r[c].w, q4v.w);
        }
        *(float4*)&sPS[(w << 7) + p0] = s4;
        *(float4*)&sPQ[(w << 7) + p0] = q4v;
        __syncthreads();

        if (t < 128) {
            float S = 0.f, Q = 0.f;
#pragma unroll
            for (int ww = 0; ww < 16; ww++) {
                S += sPS[(ww << 7) + t];
                Q += sPQ[(ww << 7) + t];
            }
            float mu = S * (1.0f / H_);
            float var = Q * (1.0f / H_) - mu * mu;
            sMu[t] = mu;
            sRs[t] = rsqrtf(var + 1e-5f);
        }
        __syncthreads();

        float4 mu4 = *(const float4*)&sMu[p0];
        float4 rs4 = *(const float4*)&sRs[p0];
        if (!FINAL) {
#pragma unroll
            for (int c = 0; c < 8; c++) {
                int ch = woff + c;
                float lw = sLnw[ch], lb = sLnb[ch];
                float4 v;
                v.x = (r[c].x - mu4.x) * rs4.x * lw + lb;
                v.y = (r[c].y - mu4.y) * rs4.y * lw + lb;
                v.z = (r[c].z - mu4.z) * rs4.z * lw + lb;
                v.w = (r[c].w - mu4.w) * rs4.w * lw + lb;
                *(float4*)&g_u[ubase + (ch << 12) + l0 + p0] = v;
            }
        } else {
            float4 o[8];
#pragma unroll
            for (int c = 0; c < 8; c++) {
                int ch = woff + c;
                float lw = sLnw[ch], lb = sLnb[ch];
                o[c].x = (r[c].x - mu4.x) * rs4.x * lw + lb;
                o[c].y = (r[c].y - mu4.y) * rs4.y * lw + lb;
                o[c].z = (r[c].z - mu4.z) * rs4.z * lw + lb;
                o[c].w = (r[c].w - mu4.w) * rs4.w * lw + lb;
            }
            // emb (b, l, h) direct write: 2 float4 per position
            size_t ebase = ((size_t)(b * L_ + l0 + p0)) * H_ + woff;
            *(float4*)&emb[ebase] =
                make_float4(o[0].x, o[1].x, o[2].x, o[3].x);
            *(float4*)&emb[ebase + 4] =
                make_float4(o[4].x, o[5].x, o[6].x, o[7].x);
            *(float4*)&emb[ebase + H_] =
                make_float4(o[0].y, o[1].y, o[2].y, o[3].y);
            *(float4*)&emb[ebase + H_ + 4] =
                make_float4(o[4].y, o[5].y, o[6].y, o[7].y);
            *(float4*)&emb[ebase + 2 * H_] =
                make_float4(o[0].z, o[1].z, o[2].z, o[3].z);
            *(float4*)&emb[ebase + 2 * H_ + 4] =
                make_float4(o[4].z, o[5].z, o[6].z, o[7].z);
            *(float4*)&emb[ebase + 3 * H_] =
                make_float4(o[0].w, o[1].w, o[2].w, o[3].w);
            *(float4*)&emb[ebase + 3 * H_ + 4] =
                make_float4(o[4].w, o[5].w, o[6].w, o[7].w);
            // deterministic pool partials: per-channel warp reduce
            int pslot = tile & 31;
#pragma unroll
            for (int c = 0; c < 8; c++) {
                float sc = o[c].x + o[c].y + o[c].z + o[c].w;
#pragma unroll
                for (int m = 16; m > 0; m >>= 1)
                    sc += __shfl_xor_sync(0xffffffffu, sc, m);
                if (lane == 0)
                    g_poolpart[(((b << 7) + woff + c) << 5) + pslot] = sc;
            }
        }
    }
}

__global__ void __launch_bounds__(512, 1)
glu_ln_kernel(const float* __restrict__ conv_w_l,
              const float* __restrict__ conv_b_l,
              const float* __restrict__ ln_w_l,
              const float* __restrict__ ln_b_l) {
    glu_body<0>(conv_w_l, conv_b_l, ln_w_l, ln_b_l, nullptr);
}

__global__ void __launch_bounds__(512, 1)
glu_ln_final_kernel(const float* __restrict__ conv_w_l,
                    const float* __restrict__ conv_b_l,
                    const float* __restrict__ ln_w_l,
                    const float* __restrict__ ln_b_l,
                    float* __restrict__ emb) {
    glu_body<1>(conv_w_l, conv_b_l, ln_w_l, ln_b_l, emb);
}

// ---------------- kernel 4: pool partial reduce ------------------------------
__global__ void pool2_kernel() {
    int idx = blockIdx.x * 256 + threadIdx.x;   // 0..4095
    if (idx >= B_ * H_) return;
    const float* p = g_poolpart + ((size_t)idx << 5);
    float s = 0.f;
#pragma unroll
    for (int i = 0; i < 32; i++) s += p[i];
    g_pool[idx] = s * (1.0f / L_);
}

// ---------------- kernel 5: decoder -----------------------------------------
__global__ void decode_kernel(const float* __restrict__ dec_w,
                              const float* __restrict__ dec_b,
                              float* __restrict__ pred) {
    int t = threadIdx.x;
    if (t >= B_ * DOUT) return;
    int b = t >> 3, o = t & 7;
    float acc = dec_b[o];
    for (int h = 0; h < H_; h++)
        acc = fmaf(dec_w[o * H_ + h], g_pool[b * H_ + h], acc);
    pred[t] = 1.0f / (1.0f + expf(-acc));
}

// ---------------- launch ------------------------------------------------------
extern "C" void kernel_launch(void* const* d_in, const int* in_sizes, int n_in,
                              void* d_out, int out_size) {
    const float* x          = (const float*)d_in[0];
    // d_in[1] = times (unused)
    const float* enc_w      = (const float*)d_in[2];
    const float* enc_b      = (const float*)d_in[3];
    const float* log_dt     = (const float*)d_in[4];
    const float* log_A_real = (const float*)d_in[5];
    const float* A_imag     = (const float*)d_in[6];
    const float* C_re       = (const float*)d_in[7];
    const float* C_im       = (const float*)d_in[8];
    const float* Dskip      = (const float*)d_in[9];
    const float* conv_w     = (const float*)d_in[10];
    const float* conv_b     = (const float*)d_in[11];
    const float* ln_w       = (const float*)d_in[12];
    const float* ln_b       = (const float*)d_in[13];
    const float* dec_w      = (const float*)d_in[14];
    const float* dec_b      = (const float*)d_in[15];

    float* out = (float*)d_out;
    float* pred = out;           // (B, DOUT) = 256 floats
    float* emb  = out + B_ * DOUT;

    static const size_t glu_smem = GLU_SMEM_FLOATS * sizeof(float);
    cudaFuncSetAttribute(glu_ln_kernel,
                         cudaFuncAttributeMaxDynamicSharedMemorySize,
                         (int)glu_smem);
    cudaFuncSetAttribute(glu_ln_final_kernel,
                         cudaFuncAttributeMaxDynamicSharedMemorySize,
                         (int)glu_smem);

    precompute_kernel<<<(NL_ * H_ * N2_ + 255) / 256, 256>>>(
        log_dt, log_A_real, A_imag, C_re, C_im);

    encoder_kernel<<<dim3(L_ / 64, B_), 256>>>(x, enc_w, enc_b);

    for (int l = 0; l < NL_ - 1; l++) {
        scan_kernel<<<512, 128>>>(l, Dskip + l * H_);
        glu_ln_kernel<<<GLU_GRID, 512, glu_smem>>>(
            conv_w + (size_t)l * 2 * H_ * H_,
            conv_b + (size_t)l * 2 * H_,
            ln_w + (size_t)l * H_,
            ln_b + (size_t)l * H_);
    }
    {
        int l = NL_ - 1;
        scan_kernel<<<512, 128>>>(l, Dskip + l * H_);
        glu_ln_final_kernel<<<GLU_GRID, 512, glu_smem>>>(
            conv_w + (size_t)l * 2 * H_ * H_,
            conv_b + (size_t)l * 2 * H_,
            ln_w + (size_t)l * H_,
            ln_b + (size_t)l * H_,
            emb);
    }

    pool2_kernel<<<16, 256>>>();
    decode_kernel<<<1, 256>>>(dec_w, dec_b, pred);
}

// round 16
// speedup vs baseline: 1.1328x; 1.0323x over previous
#include <cuda_runtime.h>
#include <math.h>
#include <stdint.h>

// Problem dims
#define B_   32
#define L_   4096
#define DIN  16
#define H_   128
#define N2_  32
#define NL_  4
#define DOUT 8

// ---------------- scratch (device globals; no allocations allowed) ----------
__device__ float g_u[B_ * H_ * L_];       // running activation, (b,h,l)
__device__ float g_y[B_ * H_ * L_];       // conv+gelu output, (b,h,l)
__device__ float g_wre[NL_ * H_ * N2_];
__device__ float g_wim[NL_ * H_ * N2_];
__device__ float g_c1[NL_ * H_ * N2_];
__device__ float g_c2[NL_ * H_ * N2_];
__device__ float g_pool[B_ * H_];
__device__ float g_poolpart[B_ * H_ * 32];

typedef unsigned long long u64;

// ---------------- f32x2 packed FMA helpers (Blackwell FFMA2) ----------------
__device__ __forceinline__ u64 pack2(float a, float b) {
    u64 r;
    asm("mov.b64 %0, {%1,%2};" : "=l"(r) : "f"(a), "f"(b));
    return r;
}
__device__ __forceinline__ void unpack2(u64 v, float& a, float& b) {
    asm("mov.b64 {%0,%1}, %2;" : "=f"(a), "=f"(b) : "l"(v));
}
__device__ __forceinline__ u64 fma2(u64 a, u64 b, u64 c) {
    u64 d;
    asm("fma.rn.f32x2 %0, %1, %2, %3;" : "=l"(d) : "l"(a), "l"(b), "l"(c));
    return d;
}

__device__ __forceinline__ float sigmoidf_(float x) {
    return 1.0f / (1.0f + expf(-x));
}

__device__ __forceinline__ void cp16(unsigned saddr, const void* gaddr) {
    asm volatile("cp.async.cg.shared.global [%0], [%1], 16;"
                 :: "r"(saddr), "l"(gaddr));
}
__device__ __forceinline__ void cp_commit() {
    asm volatile("cp.async.commit_group;");
}
__device__ __forceinline__ void cp_wait1() {
    asm volatile("cp.async.wait_group 1;");
}

// ---------------- kernel 0: precompute SSM coefficients ---------------------
__global__ void precompute_kernel(const float* __restrict__ log_dt,
                                  const float* __restrict__ log_A_real,
                                  const float* __restrict__ A_imag,
                                  const float* __restrict__ C_re,
                                  const float* __restrict__ C_im) {
    int idx = blockIdx.x * blockDim.x + threadIdx.x;   // NL*H*N2 = 16384
    if (idx >= NL_ * H_ * N2_) return;
    int l = idx / (H_ * N2_);
    int h = (idx / N2_) % H_;

    float dt  = expf(log_dt[l * H_ + h]);
    float are = -expf(log_A_real[idx]);
    float aim = A_imag[idx];
    float dre = dt * are;
    float dim = dt * aim;
    float m   = expf(dre);
    float wre = m * cosf(dim);
    float wim = m * sinf(dim);
    // (w - 1) / A
    float nre = wre - 1.0f, nim = wim;
    float den = are * are + aim * aim;
    float inv = 1.0f / den;
    float qre = (nre * are + nim * aim) * inv;
    float qim = (nim * are - nre * aim) * inv;
    float cre = C_re[idx], cim = C_im[idx];
    float tre = cre * qre - cim * qim;
    float tim = cre * qim + cim * qre;
    g_wre[idx] = wre;
    g_wim[idx] = wim;
    g_c1[idx]  = 2.0f * tre;
    g_c2[idx]  = -2.0f * tim;
}

// ---------------- kernel 1: encoder  u[b,h,l] = x[b,l,:]·enc_w[h,:] + b -----
__global__ void encoder_kernel(const float* __restrict__ x,
                               const float* __restrict__ enc_w,
                               const float* __restrict__ enc_b) {
    __shared__ float sx[64 * 17];   // [p][d], padded
    __shared__ float sw[H_ * DIN];
    __shared__ float sb[H_];
    int t = threadIdx.x;            // 256
    int b = blockIdx.y;
    int l0 = blockIdx.x * 64;

    const float* xb = x + ((size_t)b * L_ + l0) * DIN;
    for (int i = t; i < 64 * DIN; i += 256) {
        int p = i >> 4, d = i & 15;
        sx[p * 17 + d] = xb[i];
    }
    for (int i = t; i < H_ * DIN; i += 256) sw[i] = enc_w[i];
    if (t < H_) sb[t] = enc_b[t];
    __syncthreads();

    int ubase = b * H_ * L_;
    for (int i = t; i < H_ * 64; i += 256) {
        int h = i >> 6, p = i & 63;
        float acc = sb[h];
#pragma unroll
        for (int d = 0; d < DIN; d++)
            acc = fmaf(sw[(h << 4) + d], sx[p * 17 + d], acc);
        g_u[ubase + (h << 12) + l0 + p] = acc;
    }
}

// ---------------- kernel 2: SSM scan + D skip + GELU (v8: pipelined) --------
// 16 lanes/seq, 2 complex states/lane (one f32x2 pair), 2 seqs/warp.
// Software pipelining: recurrence for block k+1 is issued BEFORE the
// shuffle-reduce of block k, so the two serial chains overlap.
__global__ void __launch_bounds__(128)
scan_kernel(int layer, const float* __restrict__ Dl) {
    const unsigned F = 0xffffffffu;
    const u64 Z0 = 0ull;
    int t = threadIdx.x;                    // 128
    int warpId = blockIdx.x * 4 + (t >> 5); // 0..2047
    int lane = t & 31;
    int lane16 = lane & 15;
    int g = lane >> 4;                      // 0/1
    int seq = warpId * 2 + g;               // 0 .. B*H-1
    int h = seq & (H_ - 1);

    const float* z = g_u + (size_t)seq * L_;
    float* yo = g_y + (size_t)seq * L_;

    int cb = layer * (H_ * N2_) + h * N2_ + lane16 * 2;
    u64 wre  = pack2(g_wre[cb], g_wre[cb + 1]);
    u64 wim  = pack2(g_wim[cb], g_wim[cb + 1]);
    u64 nwim = pack2(-g_wim[cb], -g_wim[cb + 1]);
    u64 d1   = pack2(g_c1[cb], g_c1[cb + 1]);
    u64 d2   = pack2(g_c2[cb], g_c2[cb + 1]);
    float Dh = Dl[h];

    u64 sre = Z0, sim = Z0;
    bool q8 = (lane16 & 8) != 0;
    bool q4 = (lane16 & 4) != 0;
    bool q2 = (lane16 & 2) != 0;
    bool q1 = (lane16 & 1) != 0;

    const float4* z4 = (const float4*)z;

    // ---- preamble: recurrence on block 0 ----
    float sp[16];
    {
        float4 a0 = z4[0], a1 = z4[1], a2 = z4[2], a3 = z4[3];
        float zc[16] = {a0.x, a0.y, a0.z, a0.w,  a1.x, a1.y, a1.z, a1.w,
                        a2.x, a2.y, a2.z, a2.w,  a3.x, a3.y, a3.z, a3.w};
#pragma unroll
        for (int j = 0; j < 16; j++) {
            u64 z2 = pack2(zc[j], zc[j]);
            u64 nre = fma2(wre, sre, fma2(nwim, sim, z2));
            u64 nim = fma2(wre, sim, fma2(wim, sre, Z0));
            sre = nre; sim = nim;
            u64 d = fma2(d1, sre, fma2(d2, sim, Z0));
            float lo, hi;
            unpack2(d, lo, hi);
            sp[j] = lo + hi;
        }
    }
    float zown_c = z[lane16];

    for (int t0 = 0; t0 < L_ - 16; t0 += 16) {
        // load next z block + own-z
        int nb = (t0 + 16) >> 2;
        float4 b0 = z4[nb], b1 = z4[nb + 1], b2 = z4[nb + 2], b3 = z4[nb + 3];
        float zown_n = z[t0 + 16 + lane16];

        // recurrence for block k+1 (independent of sp reduce below)
        float sc[16];
        {
            float zc[16] = {b0.x, b0.y, b0.z, b0.w,  b1.x, b1.y, b1.z, b1.w,
                            b2.x, b2.y, b2.z, b2.w,  b3.x, b3.y, b3.z, b3.w};
#pragma unroll
            for (int j = 0; j < 16; j++) {
                u64 z2 = pack2(zc[j], zc[j]);
                u64 nre = fma2(wre, sre, fma2(nwim, sim, z2));
                u64 nim = fma2(wre, sim, fma2(wim, sre, Z0));
                sre = nre; sim = nim;
                u64 d = fma2(d1, sre, fma2(d2, sim, Z0));
                float lo, hi;
                unpack2(d, lo, hi);
                sc[j] = lo + hi;
            }
        }

        // reduce block k (sp) — overlaps with recurrence above in issue order
#pragma unroll
        for (int r = 0; r < 8; r++) {
            float send = q8 ? sp[r] : sp[r + 8];
            float recv = __shfl_xor_sync(F, send, 8);
            sp[r] = (q8 ? sp[r + 8] : sp[r]) + recv;
        }
#pragma unroll
        for (int r = 0; r < 4; r++) {
            float send = q4 ? sp[r] : sp[r + 4];
            float recv = __shfl_xor_sync(F, send, 4);
            sp[r] = (q4 ? sp[r + 4] : sp[r]) + recv;
        }
#pragma unroll
        for (int r = 0; r < 2; r++) {
            float send = q2 ? sp[r] : sp[r + 2];
            float recv = __shfl_xor_sync(F, send, 2);
            sp[r] = (q2 ? sp[r + 2] : sp[r]) + recv;
        }
        {
            float send = q1 ? sp[0] : sp[1];
            float recv = __shfl_xor_sync(F, send, 1);
            sp[0] = (q1 ? sp[1] : sp[0]) + recv;
        }

        float yraw = fmaf(Dh, zown_c, sp[0]);
        float gv = 0.5f * yraw * (1.0f + erff(yraw * 0.7071067811865475f));
        yo[t0 + lane16] = gv;

#pragma unroll
        for (int j = 0; j < 16; j++) sp[j] = sc[j];
        zown_c = zown_n;
    }

    // ---- tail: reduce last block ----
#pragma unroll
    for (int r = 0; r < 8; r++) {
        float send = q8 ? sp[r] : sp[r + 8];
        float recv = __shfl_xor_sync(F, send, 8);
        sp[r] = (q8 ? sp[r + 8] : sp[r]) + recv;
    }
#pragma unroll
    for (int r = 0; r < 4; r++) {
        float send = q4 ? sp[r] : sp[r + 4];
        float recv = __shfl_xor_sync(F, send, 4);
        sp[r] = (q4 ? sp[r + 4] : sp[r]) + recv;
    }
#pragma unroll
    for (int r = 0; r < 2; r++) {
        float send = q2 ? sp[r] : sp[r + 2];
        float recv = __shfl_xor_sync(F, send, 2);
        sp[r] = (q2 ? sp[r + 2] : sp[r]) + recv;
    }
    {
        float send = q1 ? sp[0] : sp[1];
        float recv = __shfl_xor_sync(F, send, 1);
        sp[0] = (q1 ? sp[1] : sp[0]) + recv;
    }
    float yraw = fmaf(Dh, zown_c, sp[0]);
    float gv = 0.5f * yraw * (1.0f + erff(yraw * 0.7071067811865475f));
    yo[L_ - 16 + lane16] = gv;
}

// ---------------- kernel 3: PERSISTENT fused 1x1 conv -> GLU -> LN ----------
// NOW 1024 threads (32 warps = 8/SMSP) for 2x occupancy; warp w owns
// a-rows [4w,4w+4) and g-rows [128+4w,...); acc[4][4].
#define WT_STRIDE 260
#define TILE_P 128
#define CH_H   32
#define N_TILES (B_ * (L_ / TILE_P))     // 1024
#define GLU_GRID 148
#define GLU_SMEM_FLOATS (33280 + 8192 + 4096 + 4096 + 256 + 256 + 256)

// Shared GEMM + GLU + LN-stats body; FINAL selects the epilogue.
template <int FINAL>
__device__ __forceinline__ void glu_body(
    const float* __restrict__ conv_w_l,
    const float* __restrict__ conv_b_l,
    const float* __restrict__ ln_w_l,
    const float* __restrict__ ln_b_l,
    float* __restrict__ emb) {
    extern __shared__ float sm[];
    float* sWt   = sm;                 // 128*260 transposed weights [h][o]
    float* sYa   = sm + 33280;         // 4096 : y chunk [h'][p] (32h x 128p)
    float* sYb   = sm + 37376;         // 4096
    float* sPS   = sm + 41472;         // 4096 : [warp][p]
    float* sPQ   = sm + 45568;         // 4096
    float* sBias = sm + 49664;         // 256
    float* sLnw  = sm + 49920;         // 128
    float* sLnb  = sm + 50048;         // 128
    float* sMu   = sm + 50176;         // 128
    float* sRs   = sm + 50304;         // 128

    int t = threadIdx.x;               // 1024
    int w = t >> 5, lane = t & 31;

    // ---- one-time staging: transposed weights (1024 threads) ----
    {
        int hh = t & 127;
        int oqb = (t >> 7) << 3;       // 0,8,...,56
#pragma unroll
        for (int k = 0; k < 8; k++) {
            int o = (oqb + k) << 2;
            float4 v;
            v.x = conv_w_l[(o + 0) * 128 + hh];
            v.y = conv_w_l[(o + 1) * 128 + hh];
            v.z = conv_w_l[(o + 2) * 128 + hh];
            v.w = conv_w_l[(o + 3) * 128 + hh];
            *(float4*)&sWt[hh * WT_STRIDE + o] = v;
        }
    }
    if (t < 256) sBias[t] = conv_b_l[t];
    if (t < 128) { sLnw[t] = ln_w_l[t]; sLnb[t] = ln_b_l[t]; }

    int p0 = lane << 2;                // 4 positions per lane
    int woff = w << 2;                 // warp channel base (0..124)

    // ---- prefetch chunk 0 of first tile ----
    int tile = blockIdx.x;
    {
        int b = tile >> 5, l0 = (tile & 31) << 7;
        int ub = b * H_ * L_ + l0;
        int h = t >> 5, p4 = t & 31;   // 1024 float4 per chunk, 1 per thread
        cp16((unsigned)__cvta_generic_to_shared(&sYa[(h << 7) + (p4 << 2)]),
             &g_y[ub + (h << 12) + (p4 << 2)]);
    }
    cp_commit();
    int cur = 0;

    for (; tile < N_TILES; tile += GLU_GRID) {
        int b = tile >> 5, l0 = (tile & 31) << 7;
        int ubase = b * H_ * L_;

        u64 acc[4][4];                 // [pair: 0-1 = a, 2-3 = g][position]
#pragma unroll
        for (int j = 0; j < 4; j++)
#pragma unroll
            for (int p = 0; p < 4; p++) acc[j][p] = 0ull;

#pragma unroll
        for (int c = 0; c < 4; c++) {
            float* bufc = cur ? sYb : sYa;
            float* bufn = cur ? sYa : sYb;
            // prefetch next chunk (or chunk 0 of the next tile)
            int ptile = (c < 3) ? tile : tile + GLU_GRID;
            int pch   = (c < 3) ? c + 1 : 0;
            if (ptile < N_TILES) {
                int pb = ptile >> 5, pl0 = (ptile & 31) << 7;
                int ub = pb * H_ * L_ + (pch * CH_H << 12) + pl0;
                int h = t >> 5, p4 = t & 31;
                cp16((unsigned)__cvta_generic_to_shared(
                         &bufn[(h << 7) + (p4 << 2)]),
                     &g_y[ub + (h << 12) + (p4 << 2)]);
            }
            cp_commit();
            cp_wait1();                // current chunk resident
            __syncthreads();

            int hbase = c * CH_H;
#pragma unroll 4
            for (int hh = 0; hh < CH_H; hh++) {
                float4 yv = *(const float4*)&bufc[(hh << 7) + p0];
                u64 ys0 = pack2(yv.x, yv.x);
                u64 ys1 = pack2(yv.y, yv.y);
                u64 ys2 = pack2(yv.z, yv.z);
                u64 ys3 = pack2(yv.w, yv.w);
                const float* wr = &sWt[(hbase + hh) * WT_STRIDE + woff];
                ulonglong2 wa = *(const ulonglong2*)(wr);        // a pairs
                ulonglong2 wg = *(const ulonglong2*)(wr + 128);  // g pairs
                u64 wp[4] = {wa.x, wa.y, wg.x, wg.y};
#pragma unroll
                for (int j = 0; j < 4; j++) {
                    acc[j][0] = fma2(wp[j], ys0, acc[j][0]);
                    acc[j][1] = fma2(wp[j], ys1, acc[j][1]);
                    acc[j][2] = fma2(wp[j], ys2, acc[j][2]);
                    acc[j][3] = fma2(wp[j], ys3, acc[j][3]);
                }
            }
            __syncthreads();           // all reads done before buffer refill
            cur ^= 1;
        }

        // ---- GLU + residual in registers (4 channels per warp) ----
        float4 r[4];
        float4 s4 = make_float4(0.f, 0.f, 0.f, 0.f);
        float4 q4v = make_float4(0.f, 0.f, 0.f, 0.f);
#pragma unroll
        for (int c = 0; c < 4; c++) {
            int j = c >> 1;
            int ch = woff + c;
            float a0, a1, a2, a3, g0, g1, g2, g3;
            if (c & 1) {
                float xx;
                unpack2(acc[j][0], xx, a0);
                unpack2(acc[j][1], xx, a1);
                unpack2(acc[j][2], xx, a2);
                unpack2(acc[j][3], xx, a3);
                unpack2(acc[j + 2][0], xx, g0);
                unpack2(acc[j + 2][1], xx, g1);
                unpack2(acc[j + 2][2], xx, g2);
                unpack2(acc[j + 2][3], xx, g3);
            } else {
                float xx;
                unpack2(acc[j][0], a0, xx);
                unpack2(acc[j][1], a1, xx);
                unpack2(acc[j][2], a2, xx);
                unpack2(acc[j][3], a3, xx);
                unpack2(acc[j + 2][0], g0, xx);
                unpack2(acc[j + 2][1], g1, xx);
                unpack2(acc[j + 2][2], g2, xx);
                unpack2(acc[j + 2][3], g3, xx);
            }
            float ba = sBias[ch], bg = sBias[128 + ch];
            float4 u4 = *(const float4*)&g_u[ubase + (ch << 12) + l0 + p0];
            r[c].x = fmaf(a0 + ba, sigmoidf_(g0 + bg), u4.x);
            r[c].y = fmaf(a1 + ba, sigmoidf_(g1 + bg), u4.y);
            r[c].z = fmaf(a2 + ba, sigmoidf_(g2 + bg), u4.z);
            r[c].w = fmaf(a3 + ba, sigmoidf_(g3 + bg), u4.w);
            s4.x += r[c].x; s4.y += r[c].y; s4.z += r[c].z; s4.w += r[c].w;
            q4v.x = fmaf(r[c].x, r[c].x, q4v.x);
            q4v.y = fmaf(r[c].y, r[c].y, q4v.y);
            q4v.z = fmaf(r[c].z, r[c].z, q4v.z);
            q4v.w = fmaf(r[c].w, r[c].w, q4v.w);
        }
        *(float4*)&sPS[(w << 7) + p0] = s4;
        *(float4*)&sPQ[(w << 7) + p0] = q4v;
        __syncthreads();

        if (t < 128) {
            float S = 0.f, Q = 0.f;
#pragma unroll
            for (int ww = 0; ww < 32; ww++) {
                S += sPS[(ww << 7) + t];
                Q += sPQ[(ww << 7) + t];
            }
            float mu = S * (1.0f / H_);
            float var = Q * (1.0f / H_) - mu * mu;
            sMu[t] = mu;
            sRs[t] = rsqrtf(var + 1e-5f);
        }
        __syncthreads();

        float4 mu4 = *(const float4*)&sMu[p0];
        float4 rs4 = *(const float4*)&sRs[p0];
        if (!FINAL) {
#pragma unroll
            for (int c = 0; c < 4; c++) {
                int ch = woff + c;
                float lw = sLnw[ch], lb = sLnb[ch];
                float4 v;
                v.x = (r[c].x - mu4.x) * rs4.x * lw + lb;
                v.y = (r[c].y - mu4.y) * rs4.y * lw + lb;
                v.z = (r[c].z - mu4.z) * rs4.z * lw + lb;
                v.w = (r[c].w - mu4.w) * rs4.w * lw + lb;
                *(float4*)&g_u[ubase + (ch << 12) + l0 + p0] = v;
            }
        } else {
            float4 o[4];
#pragma unroll
            for (int c = 0; c < 4; c++) {
                int ch = woff + c;
                float lw = sLnw[ch], lb = sLnb[ch];
                o[c].x = (r[c].x - mu4.x) * rs4.x * lw + lb;
                o[c].y = (r[c].y - mu4.y) * rs4.y * lw + lb;
                o[c].z = (r[c].z - mu4.z) * rs4.z * lw + lb;
                o[c].w = (r[c].w - mu4.w) * rs4.w * lw + lb;
            }
            // emb (b, l, h) direct write: 1 float4 (4 channels) per position
            size_t ebase = ((size_t)(b * L_ + l0 + p0)) * H_ + woff;
            *(float4*)&emb[ebase] =
                make_float4(o[0].x, o[1].x, o[2].x, o[3].x);
            *(float4*)&emb[ebase + H_] =
                make_float4(o[0].y, o[1].y, o[2].y, o[3].y);
            *(float4*)&emb[ebase + 2 * H_] =
                make_float4(o[0].z, o[1].z, o[2].z, o[3].z);
            *(float4*)&emb[ebase + 3 * H_] =
                make_float4(o[0].w, o[1].w, o[2].w, o[3].w);
            // deterministic pool partials: per-channel warp reduce
            int pslot = tile & 31;
#pragma unroll
            for (int c = 0; c < 4; c++) {
                float sc = o[c].x + o[c].y + o[c].z + o[c].w;
#pragma unroll
                for (int m = 16; m > 0; m >>= 1)
                    sc += __shfl_xor_sync(0xffffffffu, sc, m);
                if (lane == 0)
                    g_poolpart[(((b << 7) + woff + c) << 5) + pslot] = sc;
            }
        }
    }
}

__global__ void __launch_bounds__(1024, 1)
glu_ln_kernel(const float* __restrict__ conv_w_l,
              const float* __restrict__ conv_b_l,
              const float* __restrict__ ln_w_l,
              const float* __restrict__ ln_b_l) {
    glu_body<0>(conv_w_l, conv_b_l, ln_w_l, ln_b_l, nullptr);
}

__global__ void __launch_bounds__(1024, 1)
glu_ln_final_kernel(const float* __restrict__ conv_w_l,
                    const float* __restrict__ conv_b_l,
                    const float* __restrict__ ln_w_l,
                    const float* __restrict__ ln_b_l,
                    float* __restrict__ emb) {
    glu_body<1>(conv_w_l, conv_b_l, ln_w_l, ln_b_l, emb);
}

// ---------------- kernel 4: pool partial reduce ------------------------------
__global__ void pool2_kernel() {
    int idx = blockIdx.x * 256 + threadIdx.x;   // 0..4095
    if (idx >= B_ * H_) return;
    const float* p = g_poolpart + ((size_t)idx << 5);
    float s = 0.f;
#pragma unroll
    for (int i = 0; i < 32; i++) s += p[i];
    g_pool[idx] = s * (1.0f / L_);
}

// ---------------- kernel 5: decoder -----------------------------------------
__global__ void decode_kernel(const float* __restrict__ dec_w,
                              const float* __restrict__ dec_b,
                              float* __restrict__ pred) {
    int t = threadIdx.x;
    if (t >= B_ * DOUT) return;
    int b = t >> 3, o = t & 7;
    float acc = dec_b[o];
    for (int h = 0; h < H_; h++)
        acc = fmaf(dec_w[o * H_ + h], g_pool[b * H_ + h], acc);
    pred[t] = 1.0f / (1.0f + expf(-acc));
}

// ---------------- launch ------------------------------------------------------
extern "C" void kernel_launch(void* const* d_in, const int* in_sizes, int n_in,
                              void* d_out, int out_size) {
    const float* x          = (const float*)d_in[0];
    // d_in[1] = times (unused)
    const float* enc_w      = (const float*)d_in[2];
    const float* enc_b      = (const float*)d_in[3];
    const float* log_dt     = (const float*)d_in[4];
    const float* log_A_real = (const float*)d_in[5];
    const float* A_imag     = (const float*)d_in[6];
    const float* C_re       = (const float*)d_in[7];
    const float* C_im       = (const float*)d_in[8];
    const float* Dskip      = (const float*)d_in[9];
    const float* conv_w     = (const float*)d_in[10];
    const float* conv_b     = (const float*)d_in[11];
    const float* ln_w       = (const float*)d_in[12];
    const float* ln_b       = (const float*)d_in[13];
    const float* dec_w      = (const float*)d_in[14];
    const float* dec_b      = (const float*)d_in[15];

    float* out = (float*)d_out;
    float* pred = out;           // (B, DOUT) = 256 floats
    float* emb  = out + B_ * DOUT;

    static const size_t glu_smem = GLU_SMEM_FLOATS * sizeof(float);
    cudaFuncSetAttribute(glu_ln_kernel,
                         cudaFuncAttributeMaxDynamicSharedMemorySize,
                         (int)glu_smem);
    cudaFuncSetAttribute(glu_ln_final_kernel,
                         cudaFuncAttributeMaxDynamicSharedMemorySize,
                         (int)glu_smem);

    precompute_kernel<<<(NL_ * H_ * N2_ + 255) / 256, 256>>>(
        log_dt, log_A_real, A_imag, C_re, C_im);

    encoder_kernel<<<dim3(L_ / 64, B_), 256>>>(x, enc_w, enc_b);

    for (int l = 0; l < NL_ - 1; l++) {
        scan_kernel<<<512, 128>>>(l, Dskip + l * H_);
        glu_ln_kernel<<<GLU_GRID, 1024, glu_smem>>>(
            conv_w + (size_t)l * 2 * H_ * H_,
            conv_b + (size_t)l * 2 * H_,
            ln_w + (size_t)l * H_,
            ln_b + (size_t)l * H_);
    }
    {
        int l = NL_ - 1;
        scan_kernel<<<512, 128>>>(l, Dskip + l * H_);
        glu_ln_final_kernel<<<GLU_GRID, 1024, glu_smem>>>(
            conv_w + (size_t)l * 2 * H_ * H_,
            conv_b + (size_t)l * 2 * H_,
            ln_w + (size_t)l * H_,
            ln_b + (size_t)l * H_,
            emb);
    }

    pool2_kernel<<<16, 256>>>();
    decode_kernel<<<1, 256>>>(dec_w, dec_b, pred);
}